// round 5
// baseline (speedup 1.0000x reference)
#include <cuda_runtime.h>
#include <cuda_bf16.h>

typedef unsigned long long u64;

// ---------------- f32x2 packed-math helpers (sm_103a FFMA2) ----------------
__device__ __forceinline__ u64 pack2(float lo, float hi) {
    u64 r;
    asm("mov.b64 %0, {%1, %2};" : "=l"(r)
        : "r"(__float_as_uint(lo)), "r"(__float_as_uint(hi)));
    return r;
}
__device__ __forceinline__ u64 bcast2(float v) { return pack2(v, v); }
__device__ __forceinline__ void fma2(u64& d, u64 a, u64 b) {
    asm("fma.rn.f32x2 %0, %1, %2, %0;" : "+l"(d) : "l"(a), "l"(b));
}
__device__ __forceinline__ float2 unpack2(u64 v) {
    unsigned lo, hi;
    asm("mov.b64 {%0, %1}, %2;" : "=r"(lo), "=r"(hi) : "l"(v));
    return make_float2(__uint_as_float(lo), __uint_as_float(hi));
}

// ---------------- scratch (allocation-free: __device__ globals) ----------------
__device__ float g_a1[64*32*63*63];
__device__ float g_a2[64*64*32*32];
__device__ float g_z [64*64*32*32];
__device__ float g_e [64*64*32*32];
__device__ float g_d1[64*64*64*64];
__device__ float g_d2[64*32*128*128];
__device__ double g_vq_loss;
__device__ double g_recon;

__global__ void k_zero() { g_vq_loss = 0.0; g_recon = 0.0; }

// ---------------- enc conv1: 3->32, k3 s2 p1, 125->63, relu ----------------
__global__ void k_conv1(const float* __restrict__ x, const float* __restrict__ w,
                        const float* __restrict__ b) {
    int idx = blockIdx.x * 256 + threadIdx.x;
    if (idx >= 64*32*63*63) return;
    int ow = idx % 63; int t = idx / 63;
    int oh = t % 63;  t /= 63;
    int co = t % 32;  int n = t / 32;
    float acc = b[co];
    const float* xb = x + n*3*125*125;
    const float* wb = w + co*3*9;
    #pragma unroll
    for (int ci = 0; ci < 3; ci++) {
        #pragma unroll
        for (int kh = 0; kh < 3; kh++) {
            int ih = 2*oh + kh - 1;
            if ((unsigned)ih < 125u) {
                #pragma unroll
                for (int kw = 0; kw < 3; kw++) {
                    int iw = 2*ow + kw - 1;
                    if ((unsigned)iw < 125u)
                        acc += wb[ci*9 + kh*3 + kw] * xb[(ci*125 + ih)*125 + iw];
                }
            }
        }
    }
    g_a1[idx] = fmaxf(acc, 0.f);
}

// ---------------- enc conv2: 32->64, k3 s2 p1, 63->32 (R4 form) ------
__global__ void __launch_bounds__(256) k_conv2(const float* __restrict__ w,
                                               const float* __restrict__ b) {
    __shared__ float2 wp[32][4][9];
    int bid   = blockIdx.x;              // 1024 = 64n * 8cog * 2ohhalf
    int ohh   = bid & 1;
    int cog   = (bid >> 1) & 7;
    int n     = bid >> 4;
    int co0   = cog * 8;
    for (int i = threadIdx.x; i < 32*4*9; i += 256) {
        int t  = i % 9;
        int jp = (i/9) & 3;
        int ci = i / 36;
        wp[ci][jp][t] = make_float2(w[((co0 + 2*jp)    *32 + ci)*9 + t],
                                    w[((co0 + 2*jp + 1)*32 + ci)*9 + t]);
    }
    __syncthreads();
    int q  = threadIdx.x & 15;
    int oh = ohh*16 + (threadIdx.x >> 4);
    u64 accA[4], accB[4];
    #pragma unroll
    for (int jp = 0; jp < 4; jp++) {
        u64 bv = pack2(b[co0+2*jp], b[co0+2*jp+1]);
        accA[jp] = bv; accB[jp] = bv;
    }
    const float* ib = g_a1 + n*32*63*63;
    int iwb = 4*q - 1;
    for (int ci = 0; ci < 32; ci++) {
        u64 col[3][5];
        #pragma unroll
        for (int kh = 0; kh < 3; kh++) {
            int ih = 2*oh + kh - 1;
            bool hok = (unsigned)ih < 63u;
            const float* row = ib + (ci*63 + ih)*63;
            #pragma unroll
            for (int c = 0; c < 5; c++) {
                int iw = iwb + c;
                float v = (hok && (unsigned)iw < 63u) ? row[iw] : 0.f;
                col[kh][c] = bcast2(v);
            }
        }
        #pragma unroll
        for (int kh = 0; kh < 3; kh++) {
            #pragma unroll
            for (int kw = 0; kw < 3; kw++) {
                int t = kh*3 + kw;
                #pragma unroll
                for (int jp = 0; jp < 4; jp++) {
                    u64 W = *(const u64*)&wp[ci][jp][t];
                    fma2(accA[jp], W, col[kh][kw]);
                    fma2(accB[jp], W, col[kh][kw+2]);
                }
            }
        }
    }
    int ohw = oh*32 + 2*q;
    #pragma unroll
    for (int jp = 0; jp < 4; jp++) {
        float2 a = unpack2(accA[jp]);
        float2 c = unpack2(accB[jp]);
        *(float2*)&g_a2[(n*64 + co0 + 2*jp    )*1024 + ohw]
            = make_float2(fmaxf(a.x,0.f), fmaxf(c.x,0.f));
        *(float2*)&g_a2[(n*64 + co0 + 2*jp + 1)*1024 + ohw]
            = make_float2(fmaxf(a.y,0.f), fmaxf(c.y,0.f));
    }
}

// ---------------- enc conv3: 64->64 1x1 (R1 scalar form: best measured) --
__global__ void k_conv3(const float* __restrict__ w, const float* __restrict__ b) {
    __shared__ float ws[16*64];
    int bid  = blockIdx.x;                 // 1024 = 64n * 4cog * 4tile
    int tile = bid & 3;
    int cog  = (bid >> 2) & 3;
    int n    = bid >> 4;
    int co0  = cog * 16;
    for (int i = threadIdx.x; i < 1024; i += 256) ws[i] = w[co0*64 + i];
    __syncthreads();
    int hw = tile*256 + threadIdx.x;
    float acc[16];
    #pragma unroll
    for (int j = 0; j < 16; j++) acc[j] = b[co0 + j];
    const float* ib = g_a2 + n*64*1024;
    for (int ci = 0; ci < 64; ci++) {
        float v = ib[ci*1024 + hw];
        #pragma unroll
        for (int j = 0; j < 16; j++) acc[j] += ws[j*64 + ci] * v;
    }
    #pragma unroll
    for (int j = 0; j < 16; j++) g_z[(n*64 + co0 + j)*1024 + hw] = acc[j];
}

// ---------------- VQ: argmin over 512 codes, 2 codes x even/odd ILP -------
__global__ void k_vq(const float* __restrict__ codebook) {
    __shared__ float4 cbs[128][16];
    __shared__ float  cns[128];
    __shared__ float  wsum[8];
    int n  = blockIdx.x * 256 + threadIdx.x;    // exact: 256 blocks
    int bb = n >> 10;
    int hw = n & 1023;
    const float* zb = g_z + bb*65536 + hw;
    float zv[64];
    #pragma unroll
    for (int d = 0; d < 64; d++) zv[d] = zb[d*1024];
    u64 zp[32];
    #pragma unroll
    for (int q = 0; q < 32; q++) zp[q] = pack2(zv[2*q], zv[2*q+1]);
    float best = 3.0e38f; int bidx = 0;
    for (int c = 0; c < 4; c++) {
        __syncthreads();
        const float4* src = (const float4*)(codebook + c*128*64);
        for (int i = threadIdx.x; i < 2048; i += 256)
            ((float4*)cbs)[i] = src[i];
        __syncthreads();
        if (threadIdx.x < 128) {
            const float* cc = (const float*)cbs[threadIdx.x];
            float s = 0.f;
            #pragma unroll
            for (int d = 0; d < 64; d++) s += cc[d]*cc[d];
            cns[threadIdx.x] = s;
        }
        __syncthreads();
        for (int k = 0; k < 128; k += 2) {
            const ulonglong2* ck0 = (const ulonglong2*)cbs[k];
            const ulonglong2* ck1 = (const ulonglong2*)cbs[k+1];
            u64 d0e = 0ull, d0o = 0ull, d1e = 0ull, d1o = 0ull;
            #pragma unroll
            for (int q2 = 0; q2 < 16; q2++) {
                ulonglong2 c0 = ck0[q2];
                ulonglong2 c1 = ck1[q2];
                fma2(d0e, c0.x, zp[2*q2]);
                fma2(d0o, c0.y, zp[2*q2+1]);
                fma2(d1e, c1.x, zp[2*q2]);
                fma2(d1o, c1.y, zp[2*q2+1]);
            }
            float2 a0 = unpack2(d0e), b0 = unpack2(d0o);
            float2 a1 = unpack2(d1e), b1 = unpack2(d1o);
            float dist0 = cns[k]   - 2.f*(a0.x + a0.y + b0.x + b0.y);
            float dist1 = cns[k+1] - 2.f*(a1.x + a1.y + b1.x + b1.y);
            if (dist0 < best) { best = dist0; bidx = c*128 + k; }
            if (dist1 < best) { best = dist1; bidx = c*128 + k + 1; }
        }
    }
    const float* cbest = codebook + bidx*64;
    float* eb = g_e + bb*65536 + hw;
    float ls = 0.f;
    #pragma unroll
    for (int d = 0; d < 64; d++) {
        float qv = cbest[d];
        float df = qv - zv[d];
        ls += df*df;
        eb[d*1024] = qv;
    }
    #pragma unroll
    for (int off = 16; off; off >>= 1) ls += __shfl_down_sync(0xffffffffu, ls, off);
    if ((threadIdx.x & 31) == 0) wsum[threadIdx.x >> 5] = ls;
    __syncthreads();
    if (threadIdx.x == 0) {
        float s = 0.f;
        #pragma unroll
        for (int i = 0; i < 8; i++) s += wsum[i];
        atomicAdd(&g_vq_loss, (double)s);
    }
}

// ---------------- decT1: 64->64, 32x32 -> 64x64 (R4 2-pixel core) -----------
__global__ void __launch_bounds__(256, 2) k_dec1(const float* __restrict__ w,
                                                 const float* __restrict__ b) {
    __shared__ float2 wp[64][4][9];
    int bid   = blockIdx.x;            // 1024 = 64n * 8cog * 2lhalf
    int lhalf = bid & 1;
    int cog   = (bid >> 1) & 7;
    int n     = bid >> 4;
    int co0   = cog * 8;
    int tid   = threadIdx.x;
    for (int i = tid; i < 64*4*9; i += 256) {
        int t  = i % 9;
        int jp = (i/9) & 3;
        int ci = i / 36;
        wp[ci][jp][t] = make_float2(w[(ci*64 + co0 + 2*jp    )*9 + t],
                                    w[(ci*64 + co0 + 2*jp + 1)*9 + t]);
    }
    __syncthreads();
    const int S = 32;
    const float* ib = g_e + n*64*1024;
    float* ob = g_d1 + (n*64 + co0)*4096;
    int dl = tid & 15, dm = tid >> 4;
    int l  = lhalf*16 + dl;
    int mA = dm, mB = dm + 16;
    u64 aA[4][4], aB[4][4];
    #pragma unroll
    for (int jp = 0; jp < 4; jp++) {
        u64 bv = pack2(b[co0+2*jp], b[co0+2*jp+1]);
        #pragma unroll
        for (int p = 0; p < 4; p++) { aA[jp][p] = bv; aB[jp][p] = bv; }
    }
    bool lok  = (l + 1) < S;
    bool mBok = (mB + 1) < S;
    const float* pA0 = ib + mA*S + l;
    const float* pB0 = ib + mB*S + l;
    for (int ci = 0; ci < 64; ci++) {
        const float* pA = pA0 + ci*S*S;
        const float* pB = pB0 + ci*S*S;
        u64 A00 = bcast2(pA[0]);
        u64 A01 = bcast2(lok ? pA[1] : 0.f);
        u64 A10 = bcast2(pA[S]);
        u64 A11 = bcast2(lok ? pA[S+1] : 0.f);
        u64 B00 = bcast2(pB[0]);
        u64 B01 = bcast2(lok ? pB[1] : 0.f);
        u64 B10 = bcast2(mBok ? pB[S] : 0.f);
        u64 B11 = bcast2((mBok && lok) ? pB[S+1] : 0.f);
        #pragma unroll
        for (int jp = 0; jp < 4; jp++) {
            const u64* W = (const u64*)wp[ci][jp];
            u64 w4 = W[4];
            fma2(aA[jp][0], w4, A00); fma2(aB[jp][0], w4, B00);
            u64 w3 = W[3];
            fma2(aA[jp][1], w3, A01); fma2(aB[jp][1], w3, B01);
            u64 w5 = W[5];
            fma2(aA[jp][1], w5, A00); fma2(aB[jp][1], w5, B00);
            u64 w1 = W[1];
            fma2(aA[jp][2], w1, A10); fma2(aB[jp][2], w1, B10);
            u64 w7 = W[7];
            fma2(aA[jp][2], w7, A00); fma2(aB[jp][2], w7, B00);
            u64 w0 = W[0];
            fma2(aA[jp][3], w0, A11); fma2(aB[jp][3], w0, B11);
            u64 w2 = W[2];
            fma2(aA[jp][3], w2, A10); fma2(aB[jp][3], w2, B10);
            u64 w6 = W[6];
            fma2(aA[jp][3], w6, A01); fma2(aB[jp][3], w6, B01);
            u64 w8 = W[8];
            fma2(aA[jp][3], w8, A00); fma2(aB[jp][3], w8, B00);
        }
    }
    const int O = 64;
    #pragma unroll
    for (int jp = 0; jp < 4; jp++) {
        float2 a0 = unpack2(aA[jp][0]);
        float2 a1 = unpack2(aA[jp][1]);
        float2 a2 = unpack2(aA[jp][2]);
        float2 a3 = unpack2(aA[jp][3]);
        float* o0 = ob + (2*jp)*O*O + (2*mA)*O + 2*l;
        float* o1 = o0 + O*O;
        *(float2*)(o0)     = make_float2(fmaxf(a0.x,0.f), fmaxf(a1.x,0.f));
        *(float2*)(o0 + O) = make_float2(fmaxf(a2.x,0.f), fmaxf(a3.x,0.f));
        *(float2*)(o1)     = make_float2(fmaxf(a0.y,0.f), fmaxf(a1.y,0.f));
        *(float2*)(o1 + O) = make_float2(fmaxf(a2.y,0.f), fmaxf(a3.y,0.f));
        float2 b0 = unpack2(aB[jp][0]);
        float2 b1 = unpack2(aB[jp][1]);
        float2 b2 = unpack2(aB[jp][2]);
        float2 b3 = unpack2(aB[jp][3]);
        float* q0 = ob + (2*jp)*O*O + (2*mB)*O + 2*l;
        float* q1 = q0 + O*O;
        *(float2*)(q0)     = make_float2(fmaxf(b0.x,0.f), fmaxf(b1.x,0.f));
        *(float2*)(q0 + O) = make_float2(fmaxf(b2.x,0.f), fmaxf(b3.x,0.f));
        *(float2*)(q1)     = make_float2(fmaxf(b0.y,0.f), fmaxf(b1.y,0.f));
        *(float2*)(q1 + O) = make_float2(fmaxf(b2.y,0.f), fmaxf(b3.y,0.f));
    }
}

// ---------------- decT2: 64->32, 64x64 -> 128x128, 4 pixels/thread ----------
__global__ void __launch_bounds__(256) k_dec2(const float* __restrict__ w,
                                              const float* __restrict__ b) {
    __shared__ float2 wp[64][4][9];
    int bid  = blockIdx.x;             // 1024 = 64n * 4cog * 4ltile
    int lt   = bid & 3;
    int cog  = (bid >> 2) & 3;
    int n    = bid >> 4;
    int co0  = cog * 8;
    int tid  = threadIdx.x;
    for (int i = tid; i < 64*4*9; i += 256) {
        int t  = i % 9;
        int jp = (i/9) & 3;
        int ci = i / 36;
        wp[ci][jp][t] = make_float2(w[(ci*32 + co0 + 2*jp    )*9 + t],
                                    w[(ci*32 + co0 + 2*jp + 1)*9 + t]);
    }
    __syncthreads();
    const int S = 64;
    const float* ib = g_d1 + n*64*4096;
    float* ob = g_d2 + (n*32 + co0)*16384;
    int dl = tid & 15, dm = tid >> 4;
    int l  = lt*16 + dl;
    u64 acc[4][4][4];                  // [px][jp][pos]
    #pragma unroll
    for (int jp = 0; jp < 4; jp++) {
        u64 bv = pack2(b[co0+2*jp], b[co0+2*jp+1]);
        #pragma unroll
        for (int px = 0; px < 4; px++)
            #pragma unroll
            for (int p = 0; p < 4; p++) acc[px][jp][p] = bv;
    }
    bool lok   = (l + 1) < S;
    bool mok3  = (dm != 15);           // only px3 (m=dm+48) can hit m+1==64
    const float* base0 = ib + dm*S + l;
    for (int ci = 0; ci < 64; ci++) {
        const float* cbase = base0 + ci*S*S;
        u64 P[4][4];
        #pragma unroll
        for (int px = 0; px < 4; px++) {
            const float* p = cbase + px*16*S;
            bool mok = (px < 3) | mok3;
            P[px][0] = bcast2(p[0]);
            P[px][1] = bcast2(lok ? p[1] : 0.f);
            P[px][2] = bcast2(mok ? p[S] : 0.f);
            P[px][3] = bcast2((mok && lok) ? p[S+1] : 0.f);
        }
        #pragma unroll
        for (int jp = 0; jp < 4; jp++) {
            const u64* W = (const u64*)wp[ci][jp];
            u64 w0=W[0], w1=W[1], w2=W[2], w3=W[3], w4=W[4],
                w5=W[5], w6=W[6], w7=W[7], w8=W[8];
            #pragma unroll
            for (int px = 0; px < 4; px++) {
                fma2(acc[px][jp][0], w4, P[px][0]);
                fma2(acc[px][jp][1], w3, P[px][1]);
                fma2(acc[px][jp][1], w5, P[px][0]);
                fma2(acc[px][jp][2], w1, P[px][2]);
                fma2(acc[px][jp][2], w7, P[px][0]);
                fma2(acc[px][jp][3], w0, P[px][3]);
                fma2(acc[px][jp][3], w2, P[px][2]);
                fma2(acc[px][jp][3], w6, P[px][1]);
                fma2(acc[px][jp][3], w8, P[px][0]);
            }
        }
    }
    const int O = 128;
    #pragma unroll
    for (int px = 0; px < 4; px++) {
        int m = dm + px*16;
        #pragma unroll
        for (int jp = 0; jp < 4; jp++) {
            float2 a0 = unpack2(acc[px][jp][0]);
            float2 a1 = unpack2(acc[px][jp][1]);
            float2 a2 = unpack2(acc[px][jp][2]);
            float2 a3 = unpack2(acc[px][jp][3]);
            float* o0 = ob + (2*jp)*O*O + (2*m)*O + 2*l;
            float* o1 = o0 + O*O;
            *(float2*)(o0)     = make_float2(fmaxf(a0.x,0.f), fmaxf(a1.x,0.f));
            *(float2*)(o0 + O) = make_float2(fmaxf(a2.x,0.f), fmaxf(a3.x,0.f));
            *(float2*)(o1)     = make_float2(fmaxf(a0.y,0.f), fmaxf(a1.y,0.f));
            *(float2*)(o1 + O) = make_float2(fmaxf(a2.y,0.f), fmaxf(a3.y,0.f));
        }
    }
}

// ---------------- decT3: 32->3, k2 s1 p2, 128->125, 2-px + recon loss --------
__global__ void k_dec3(const float* __restrict__ w, const float* __restrict__ bs,
                       const float* __restrict__ x, float* __restrict__ out) {
    __shared__ float ws[384];
    __shared__ float wsum[8];
    for (int i = threadIdx.x; i < 384; i += 256) ws[i] = w[i];
    __syncthreads();
    int idx = blockIdx.x * 256 + threadIdx.x;    // 504000 work items
    float lsum = 0.f;
    if (idx < 504000) {
        int q  = idx % 63; int t = idx / 63;
        int oh = t % 125;  int n = t / 125;
        int ow0 = 2*q;
        bool has1 = (ow0 != 124);
        u64 aA0[3], aB0[3], aA1[3], aB1[3];
        #pragma unroll
        for (int co = 0; co < 3; co++) { aA0[co]=0ull; aB0[co]=0ull; aA1[co]=0ull; aB1[co]=0ull; }
        const float* p0 = g_d2 + n*32*16384 + (oh+1)*128 + ow0;  // even: float2-aligned
        const u64* wsu = (const u64*)ws;
        for (int ci = 0; ci < 32; ci++) {
            const float* p = p0 + ci*16384;
            float2 r0a = *(const float2*)(p);        // cols ow0, ow0+1
            float2 r0b = *(const float2*)(p + 2);    // cols ow0+2, ow0+3
            float2 r1a = *(const float2*)(p + 128);
            float2 r1b = *(const float2*)(p + 130);
            u64 A0 = pack2(r1b.x, r1a.y);
            u64 B0 = pack2(r0b.x, r0a.y);
            u64 A1 = pack2(r1b.y, r1b.x);
            u64 B1 = pack2(r0b.y, r0b.x);
            #pragma unroll
            for (int co = 0; co < 3; co++) {
                u64 WA = wsu[ci*6 + co*2];
                u64 WB = wsu[ci*6 + co*2 + 1];
                fma2(aA0[co], WA, A0);
                fma2(aB0[co], WB, B0);
                fma2(aA1[co], WA, A1);
                fma2(aB1[co], WB, B1);
            }
        }
        #pragma unroll
        for (int co = 0; co < 3; co++) {
            float2 a = unpack2(aA0[co]);
            float2 c = unpack2(aB0[co]);
            float v0 = bs[co] + a.x + a.y + c.x + c.y;
            int oi = ((n*3 + co)*125 + oh)*125 + ow0;
            out[oi] = v0;
            float d0 = v0 - x[oi];
            lsum += d0*d0;
            if (has1) {
                float2 a1 = unpack2(aA1[co]);
                float2 c1 = unpack2(aB1[co]);
                float v1 = bs[co] + a1.x + a1.y + c1.x + c1.y;
                out[oi + 1] = v1;
                float d1 = v1 - x[oi + 1];
                lsum += d1*d1;
            }
        }
    }
    #pragma unroll
    for (int off = 16; off; off >>= 1) lsum += __shfl_down_sync(0xffffffffu, lsum, off);
    if ((threadIdx.x & 31) == 0) wsum[threadIdx.x >> 5] = lsum;
    __syncthreads();
    if (threadIdx.x == 0) {
        float s = 0.f;
        #pragma unroll
        for (int i = 0; i < 8; i++) s += wsum[i];
        atomicAdd(&g_recon, (double)s);
    }
}

// ---------------- finalize ----------------
__global__ void k_final(float* __restrict__ out) {
    double mse = g_vq_loss / (65536.0 * 64.0);
    float eq  = (float)(1.25 * mse);
    float rec = (float)g_recon;
    out[0] = eq + rec;
    out[1] = eq;
    out[2] = rec;
}

extern "C" void kernel_launch(void* const* d_in, const int* in_sizes, int n_in,
                              void* d_out, int out_size) {
    const float* x   = (const float*)d_in[0];
    const float* ew1 = (const float*)d_in[1];
    const float* eb1 = (const float*)d_in[2];
    const float* ew2 = (const float*)d_in[3];
    const float* eb2 = (const float*)d_in[4];
    const float* ew3 = (const float*)d_in[5];
    const float* eb3 = (const float*)d_in[6];
    const float* cb  = (const float*)d_in[7];
    const float* dw1 = (const float*)d_in[8];
    const float* db1 = (const float*)d_in[9];
    const float* dw2 = (const float*)d_in[10];
    const float* db2 = (const float*)d_in[11];
    const float* dw3 = (const float*)d_in[12];
    const float* db3 = (const float*)d_in[13];
    float* out = (float*)d_out;

    k_zero <<<1, 1>>>();
    k_conv1<<<(64*32*63*63 + 255)/256, 256>>>(x, ew1, eb1);
    k_conv2<<<1024, 256>>>(ew2, eb2);
    k_conv3<<<1024, 256>>>(ew3, eb3);
    k_vq   <<<256, 256>>>(cb);
    k_dec1 <<<1024, 256>>>(dw1, db1);
    k_dec2 <<<1024, 256>>>(dw2, db2);
    k_dec3 <<<(504000 + 255)/256, 256>>>(dw3, db3, x, out + 3);
    k_final<<<1, 1>>>(out);
}

// round 6
// speedup vs baseline: 1.1272x; 1.1272x over previous
#include <cuda_runtime.h>
#include <cuda_bf16.h>

typedef unsigned long long u64;

// ---------------- f32x2 packed-math helpers (sm_103a FFMA2) ----------------
__device__ __forceinline__ u64 pack2(float lo, float hi) {
    u64 r;
    asm("mov.b64 %0, {%1, %2};" : "=l"(r)
        : "r"(__float_as_uint(lo)), "r"(__float_as_uint(hi)));
    return r;
}
__device__ __forceinline__ u64 bcast2(float v) { return pack2(v, v); }
__device__ __forceinline__ void fma2(u64& d, u64 a, u64 b) {
    asm("fma.rn.f32x2 %0, %1, %2, %0;" : "+l"(d) : "l"(a), "l"(b));
}
__device__ __forceinline__ float2 unpack2(u64 v) {
    unsigned lo, hi;
    asm("mov.b64 {%0, %1}, %2;" : "=r"(lo), "=r"(hi) : "l"(v));
    return make_float2(__uint_as_float(lo), __uint_as_float(hi));
}

// ---------------- scratch (allocation-free: __device__ globals) ----------------
__device__ float g_a1[64*32*63*63];
__device__ float g_a2[64*64*32*32];
__device__ float g_z [64*64*32*32];
__device__ float g_e [64*64*32*32];
__device__ float g_d1[64*64*64*64];
__device__ float g_d2[64*32*128*128];
__device__ double g_vq_loss;
__device__ double g_recon;

__global__ void k_zero() { g_vq_loss = 0.0; g_recon = 0.0; }

// ---------------- enc conv1: 3->32, k3 s2 p1, 125->63, relu ----------------
__global__ void k_conv1(const float* __restrict__ x, const float* __restrict__ w,
                        const float* __restrict__ b) {
    int idx = blockIdx.x * 256 + threadIdx.x;
    if (idx >= 64*32*63*63) return;
    int ow = idx % 63; int t = idx / 63;
    int oh = t % 63;  t /= 63;
    int co = t % 32;  int n = t / 32;
    float acc = b[co];
    const float* xb = x + n*3*125*125;
    const float* wb = w + co*3*9;
    #pragma unroll
    for (int ci = 0; ci < 3; ci++) {
        #pragma unroll
        for (int kh = 0; kh < 3; kh++) {
            int ih = 2*oh + kh - 1;
            if ((unsigned)ih < 125u) {
                #pragma unroll
                for (int kw = 0; kw < 3; kw++) {
                    int iw = 2*ow + kw - 1;
                    if ((unsigned)iw < 125u)
                        acc += wb[ci*9 + kh*3 + kw] * xb[(ci*125 + ih)*125 + iw];
                }
            }
        }
    }
    g_a1[idx] = fmaxf(acc, 0.f);
}

// ---------------- enc conv2: 32->64, k3 s2 p1, 63->32 (R4 form) ------
__global__ void __launch_bounds__(256) k_conv2(const float* __restrict__ w,
                                               const float* __restrict__ b) {
    __shared__ float2 wp[32][4][9];
    int bid   = blockIdx.x;              // 1024 = 64n * 8cog * 2ohhalf
    int ohh   = bid & 1;
    int cog   = (bid >> 1) & 7;
    int n     = bid >> 4;
    int co0   = cog * 8;
    for (int i = threadIdx.x; i < 32*4*9; i += 256) {
        int t  = i % 9;
        int jp = (i/9) & 3;
        int ci = i / 36;
        wp[ci][jp][t] = make_float2(w[((co0 + 2*jp)    *32 + ci)*9 + t],
                                    w[((co0 + 2*jp + 1)*32 + ci)*9 + t]);
    }
    __syncthreads();
    int q  = threadIdx.x & 15;
    int oh = ohh*16 + (threadIdx.x >> 4);
    u64 accA[4], accB[4];
    #pragma unroll
    for (int jp = 0; jp < 4; jp++) {
        u64 bv = pack2(b[co0+2*jp], b[co0+2*jp+1]);
        accA[jp] = bv; accB[jp] = bv;
    }
    const float* ib = g_a1 + n*32*63*63;
    int iwb = 4*q - 1;
    for (int ci = 0; ci < 32; ci++) {
        u64 col[3][5];
        #pragma unroll
        for (int kh = 0; kh < 3; kh++) {
            int ih = 2*oh + kh - 1;
            bool hok = (unsigned)ih < 63u;
            const float* row = ib + (ci*63 + ih)*63;
            #pragma unroll
            for (int c = 0; c < 5; c++) {
                int iw = iwb + c;
                float v = (hok && (unsigned)iw < 63u) ? row[iw] : 0.f;
                col[kh][c] = bcast2(v);
            }
        }
        #pragma unroll
        for (int kh = 0; kh < 3; kh++) {
            #pragma unroll
            for (int kw = 0; kw < 3; kw++) {
                int t = kh*3 + kw;
                #pragma unroll
                for (int jp = 0; jp < 4; jp++) {
                    u64 W = *(const u64*)&wp[ci][jp][t];
                    fma2(accA[jp], W, col[kh][kw]);
                    fma2(accB[jp], W, col[kh][kw+2]);
                }
            }
        }
    }
    int ohw = oh*32 + 2*q;
    #pragma unroll
    for (int jp = 0; jp < 4; jp++) {
        float2 a = unpack2(accA[jp]);
        float2 c = unpack2(accB[jp]);
        *(float2*)&g_a2[(n*64 + co0 + 2*jp    )*1024 + ohw]
            = make_float2(fmaxf(a.x,0.f), fmaxf(c.x,0.f));
        *(float2*)&g_a2[(n*64 + co0 + 2*jp + 1)*1024 + ohw]
            = make_float2(fmaxf(a.y,0.f), fmaxf(c.y,0.f));
    }
}

// ---------------- enc conv3: 64->64 1x1 (R1 scalar form: best measured) --
__global__ void k_conv3(const float* __restrict__ w, const float* __restrict__ b) {
    __shared__ float ws[16*64];
    int bid  = blockIdx.x;                 // 1024 = 64n * 4cog * 4tile
    int tile = bid & 3;
    int cog  = (bid >> 2) & 3;
    int n    = bid >> 4;
    int co0  = cog * 16;
    for (int i = threadIdx.x; i < 1024; i += 256) ws[i] = w[co0*64 + i];
    __syncthreads();
    int hw = tile*256 + threadIdx.x;
    float acc[16];
    #pragma unroll
    for (int j = 0; j < 16; j++) acc[j] = b[co0 + j];
    const float* ib = g_a2 + n*64*1024;
    for (int ci = 0; ci < 64; ci++) {
        float v = ib[ci*1024 + hw];
        #pragma unroll
        for (int j = 0; j < 16; j++) acc[j] += ws[j*64 + ci] * v;
    }
    #pragma unroll
    for (int j = 0; j < 16; j++) g_z[(n*64 + co0 + j)*1024 + hw] = acc[j];
}

// ---------------- VQ: argmin over 512 codes, 2 codes x even/odd ILP -------
__global__ void k_vq(const float* __restrict__ codebook) {
    __shared__ float4 cbs[128][16];
    __shared__ float  cns[128];
    __shared__ float  wsum[8];
    int n  = blockIdx.x * 256 + threadIdx.x;    // exact: 256 blocks
    int bb = n >> 10;
    int hw = n & 1023;
    const float* zb = g_z + bb*65536 + hw;
    float zv[64];
    #pragma unroll
    for (int d = 0; d < 64; d++) zv[d] = zb[d*1024];
    u64 zp[32];
    #pragma unroll
    for (int q = 0; q < 32; q++) zp[q] = pack2(zv[2*q], zv[2*q+1]);
    float best = 3.0e38f; int bidx = 0;
    for (int c = 0; c < 4; c++) {
        __syncthreads();
        const float4* src = (const float4*)(codebook + c*128*64);
        for (int i = threadIdx.x; i < 2048; i += 256)
            ((float4*)cbs)[i] = src[i];
        __syncthreads();
        if (threadIdx.x < 128) {
            const float* cc = (const float*)cbs[threadIdx.x];
            float s = 0.f;
            #pragma unroll
            for (int d = 0; d < 64; d++) s += cc[d]*cc[d];
            cns[threadIdx.x] = s;
        }
        __syncthreads();
        for (int k = 0; k < 128; k += 2) {
            const ulonglong2* ck0 = (const ulonglong2*)cbs[k];
            const ulonglong2* ck1 = (const ulonglong2*)cbs[k+1];
            u64 d0e = 0ull, d0o = 0ull, d1e = 0ull, d1o = 0ull;
            #pragma unroll
            for (int q2 = 0; q2 < 16; q2++) {
                ulonglong2 c0 = ck0[q2];
                ulonglong2 c1 = ck1[q2];
                fma2(d0e, c0.x, zp[2*q2]);
                fma2(d0o, c0.y, zp[2*q2+1]);
                fma2(d1e, c1.x, zp[2*q2]);
                fma2(d1o, c1.y, zp[2*q2+1]);
            }
            float2 a0 = unpack2(d0e), b0 = unpack2(d0o);
            float2 a1 = unpack2(d1e), b1 = unpack2(d1o);
            float dist0 = cns[k]   - 2.f*(a0.x + a0.y + b0.x + b0.y);
            float dist1 = cns[k+1] - 2.f*(a1.x + a1.y + b1.x + b1.y);
            if (dist0 < best) { best = dist0; bidx = c*128 + k; }
            if (dist1 < best) { best = dist1; bidx = c*128 + k + 1; }
        }
    }
    const float* cbest = codebook + bidx*64;
    float* eb = g_e + bb*65536 + hw;
    float ls = 0.f;
    #pragma unroll
    for (int d = 0; d < 64; d++) {
        float qv = cbest[d];
        float df = qv - zv[d];
        ls += df*df;
        eb[d*1024] = qv;
    }
    #pragma unroll
    for (int off = 16; off; off >>= 1) ls += __shfl_down_sync(0xffffffffu, ls, off);
    if ((threadIdx.x & 31) == 0) wsum[threadIdx.x >> 5] = ls;
    __syncthreads();
    if (threadIdx.x == 0) {
        float s = 0.f;
        #pragma unroll
        for (int i = 0; i < 8; i++) s += wsum[i];
        atomicAdd(&g_vq_loss, (double)s);
    }
}

// =====================================================================
// decT core (R4): co-pair lanes, 2 pixels per thread (rows m, m+16)
// =====================================================================
template<int S>
__device__ __forceinline__ void dec_core(
    const float* __restrict__ ib, const float* __restrict__ w, int CO,
    const float* __restrict__ b, float* __restrict__ ob,
    int co0, int m0, int l0)
{
    __shared__ float2 wp[64][4][9];      // 18KB
    int tid = threadIdx.x;
    for (int i = tid; i < 64*4*9; i += 256) {
        int t  = i % 9;
        int jp = (i/9) & 3;
        int ci = i / 36;
        wp[ci][jp][t] = make_float2(w[(ci*CO + co0 + 2*jp    )*9 + t],
                                    w[(ci*CO + co0 + 2*jp + 1)*9 + t]);
    }
    __syncthreads();

    int dl = tid & 15, dm = tid >> 4;
    int l  = l0 + dl;
    int mA = m0 + dm;
    int mB = mA + 16;
    u64 aA[4][4], aB[4][4];
    #pragma unroll
    for (int jp = 0; jp < 4; jp++) {
        u64 bv = pack2(b[co0+2*jp], b[co0+2*jp+1]);
        #pragma unroll
        for (int p = 0; p < 4; p++) { aA[jp][p] = bv; aB[jp][p] = bv; }
    }
    bool lok  = (l  + 1) < S;
    bool mAok = (mA + 1) < S;
    bool mBok = (mB + 1) < S;
    const float* pA0 = ib + mA*S + l;
    const float* pB0 = ib + mB*S + l;
    for (int ci = 0; ci < 64; ci++) {
        const float* pA = pA0 + ci*S*S;
        const float* pB = pB0 + ci*S*S;
        u64 A00 = bcast2(pA[0]);
        u64 A01 = bcast2(lok ? pA[1] : 0.f);
        u64 A10 = bcast2(mAok ? pA[S] : 0.f);
        u64 A11 = bcast2((mAok && lok) ? pA[S+1] : 0.f);
        u64 B00 = bcast2(pB[0]);
        u64 B01 = bcast2(lok ? pB[1] : 0.f);
        u64 B10 = bcast2(mBok ? pB[S] : 0.f);
        u64 B11 = bcast2((mBok && lok) ? pB[S+1] : 0.f);
        #pragma unroll
        for (int jp = 0; jp < 4; jp++) {
            const u64* W = (const u64*)wp[ci][jp];
            u64 w4 = W[4];
            fma2(aA[jp][0], w4, A00); fma2(aB[jp][0], w4, B00);
            u64 w3 = W[3];
            fma2(aA[jp][1], w3, A01); fma2(aB[jp][1], w3, B01);
            u64 w5 = W[5];
            fma2(aA[jp][1], w5, A00); fma2(aB[jp][1], w5, B00);
            u64 w1 = W[1];
            fma2(aA[jp][2], w1, A10); fma2(aB[jp][2], w1, B10);
            u64 w7 = W[7];
            fma2(aA[jp][2], w7, A00); fma2(aB[jp][2], w7, B00);
            u64 w0 = W[0];
            fma2(aA[jp][3], w0, A11); fma2(aB[jp][3], w0, B11);
            u64 w2 = W[2];
            fma2(aA[jp][3], w2, A10); fma2(aB[jp][3], w2, B10);
            u64 w6 = W[6];
            fma2(aA[jp][3], w6, A01); fma2(aB[jp][3], w6, B01);
            u64 w8 = W[8];
            fma2(aA[jp][3], w8, A00); fma2(aB[jp][3], w8, B00);
        }
    }
    const int O = 2*S;
    #pragma unroll
    for (int jp = 0; jp < 4; jp++) {
        float2 a0 = unpack2(aA[jp][0]);
        float2 a1 = unpack2(aA[jp][1]);
        float2 a2 = unpack2(aA[jp][2]);
        float2 a3 = unpack2(aA[jp][3]);
        float* o0 = ob + (2*jp)*O*O + (2*mA)*O + 2*l;
        float* o1 = o0 + O*O;
        *(float2*)(o0)     = make_float2(fmaxf(a0.x,0.f), fmaxf(a1.x,0.f));
        *(float2*)(o0 + O) = make_float2(fmaxf(a2.x,0.f), fmaxf(a3.x,0.f));
        *(float2*)(o1)     = make_float2(fmaxf(a0.y,0.f), fmaxf(a1.y,0.f));
        *(float2*)(o1 + O) = make_float2(fmaxf(a2.y,0.f), fmaxf(a3.y,0.f));
        float2 b0 = unpack2(aB[jp][0]);
        float2 b1 = unpack2(aB[jp][1]);
        float2 b2 = unpack2(aB[jp][2]);
        float2 b3 = unpack2(aB[jp][3]);
        float* q0 = ob + (2*jp)*O*O + (2*mB)*O + 2*l;
        float* q1 = q0 + O*O;
        *(float2*)(q0)     = make_float2(fmaxf(b0.x,0.f), fmaxf(b1.x,0.f));
        *(float2*)(q0 + O) = make_float2(fmaxf(b2.x,0.f), fmaxf(b3.x,0.f));
        *(float2*)(q1)     = make_float2(fmaxf(b0.y,0.f), fmaxf(b1.y,0.f));
        *(float2*)(q1 + O) = make_float2(fmaxf(b2.y,0.f), fmaxf(b3.y,0.f));
    }
}

// decT1: 64->64, 32x32 -> 64x64
__global__ void __launch_bounds__(256, 2) k_dec1(const float* __restrict__ w,
                                                 const float* __restrict__ b) {
    int bid   = blockIdx.x;            // 1024 = 64n * 8cog * 2lhalf
    int lhalf = bid & 1;
    int cog   = (bid >> 1) & 7;
    int n     = bid >> 4;
    int co0   = cog * 8;
    dec_core<32>(g_e + n*64*1024, w, 64, b, g_d1 + (n*64 + co0)*4096,
                 co0, 0, lhalf*16);
}

// decT2: 64->32, 64x64 -> 128x128
__global__ void __launch_bounds__(256, 2) k_dec2(const float* __restrict__ w,
                                                 const float* __restrict__ b) {
    int bid  = blockIdx.x;             // 2048 = 64n * 4cog * 8tile
    int t    = bid & 7;
    int l0   = (t & 3) * 16;
    int m0   = (t >> 2) * 32;
    int cog  = (bid >> 3) & 3;
    int n    = bid >> 5;
    int co0  = cog * 8;
    dec_core<64>(g_d1 + n*64*4096, w, 32, b, g_d2 + (n*32 + co0)*16384,
                 co0, m0, l0);
}

// ---------------- decT3: 32->3, k2 s1 p2, 128->125 + recon loss (R4) --------
__global__ void k_dec3(const float* __restrict__ w, const float* __restrict__ bs,
                       const float* __restrict__ x, float* __restrict__ out) {
    __shared__ float ws[384];
    __shared__ float wsum[8];
    for (int i = threadIdx.x; i < 384; i += 256) ws[i] = w[i];
    __syncthreads();
    int idx = blockIdx.x * 256 + threadIdx.x;
    float lsum = 0.f;
    if (idx < 1000000) {
        int ow = idx % 125; int t = idx / 125;
        int oh = t % 125;   int n = t / 125;
        u64 accA[3], accB[3];
        #pragma unroll
        for (int co = 0; co < 3; co++) { accA[co] = 0ull; accB[co] = 0ull; }
        const float* ib = g_d2 + n*32*16384;
        const float* p  = ib + (oh+1)*128 + (ow+1);
        const u64* wsu = (const u64*)ws;
        for (int ci = 0; ci < 32; ci++) {
            const float* q = p + ci*16384;
            u64 A = pack2(q[129], q[128]);
            u64 B = pack2(q[1],   q[0]);
            #pragma unroll
            for (int co = 0; co < 3; co++) {
                fma2(accA[co], wsu[ci*6 + co*2    ], A);
                fma2(accB[co], wsu[ci*6 + co*2 + 1], B);
            }
        }
        #pragma unroll
        for (int co = 0; co < 3; co++) {
            float2 a = unpack2(accA[co]);
            float2 c = unpack2(accB[co]);
            float v = bs[co] + a.x + a.y + c.x + c.y;
            int oi = ((n*3 + co)*125 + oh)*125 + ow;
            out[oi] = v;
            float d = v - x[oi];
            lsum += d*d;
        }
    }
    #pragma unroll
    for (int off = 16; off; off >>= 1) lsum += __shfl_down_sync(0xffffffffu, lsum, off);
    if ((threadIdx.x & 31) == 0) wsum[threadIdx.x >> 5] = lsum;
    __syncthreads();
    if (threadIdx.x == 0) {
        float s = 0.f;
        #pragma unroll
        for (int i = 0; i < 8; i++) s += wsum[i];
        atomicAdd(&g_recon, (double)s);
    }
}

// ---------------- finalize ----------------
__global__ void k_final(float* __restrict__ out) {
    double mse = g_vq_loss / (65536.0 * 64.0);
    float eq  = (float)(1.25 * mse);
    float rec = (float)g_recon;
    out[0] = eq + rec;
    out[1] = eq;
    out[2] = rec;
}

extern "C" void kernel_launch(void* const* d_in, const int* in_sizes, int n_in,
                              void* d_out, int out_size) {
    const float* x   = (const float*)d_in[0];
    const float* ew1 = (const float*)d_in[1];
    const float* eb1 = (const float*)d_in[2];
    const float* ew2 = (const float*)d_in[3];
    const float* eb2 = (const float*)d_in[4];
    const float* ew3 = (const float*)d_in[5];
    const float* eb3 = (const float*)d_in[6];
    const float* cb  = (const float*)d_in[7];
    const float* dw1 = (const float*)d_in[8];
    const float* db1 = (const float*)d_in[9];
    const float* dw2 = (const float*)d_in[10];
    const float* db2 = (const float*)d_in[11];
    const float* dw3 = (const float*)d_in[12];
    const float* db3 = (const float*)d_in[13];
    float* out = (float*)d_out;

    k_zero <<<1, 1>>>();
    k_conv1<<<(64*32*63*63 + 255)/256, 256>>>(x, ew1, eb1);
    k_conv2<<<1024, 256>>>(ew2, eb2);
    k_conv3<<<1024, 256>>>(ew3, eb3);
    k_vq   <<<256, 256>>>(cb);
    k_dec1 <<<1024, 256>>>(dw1, db1);
    k_dec2 <<<2048, 256>>>(dw2, db2);
    k_dec3 <<<3907, 256>>>(dw3, db3, x, out + 3);
    k_final<<<1, 1>>>(out);
}

// round 7
// speedup vs baseline: 1.1752x; 1.0425x over previous
#include <cuda_runtime.h>
#include <cuda_bf16.h>

typedef unsigned long long u64;

// ---------------- f32x2 packed-math helpers (sm_103a FFMA2) ----------------
__device__ __forceinline__ u64 pack2(float lo, float hi) {
    u64 r;
    asm("mov.b64 %0, {%1, %2};" : "=l"(r)
        : "r"(__float_as_uint(lo)), "r"(__float_as_uint(hi)));
    return r;
}
__device__ __forceinline__ u64 bcast2(float v) { return pack2(v, v); }
__device__ __forceinline__ void fma2(u64& d, u64 a, u64 b) {
    asm("fma.rn.f32x2 %0, %1, %2, %0;" : "+l"(d) : "l"(a), "l"(b));
}
__device__ __forceinline__ float2 unpack2(u64 v) {
    unsigned lo, hi;
    asm("mov.b64 {%0, %1}, %2;" : "=r"(lo), "=r"(hi) : "l"(v));
    return make_float2(__uint_as_float(lo), __uint_as_float(hi));
}

// ---------------- scratch (allocation-free: __device__ globals) ----------------
__device__ float g_a1[64*32*63*63];
__device__ float g_a2[64*64*32*32];
__device__ float g_z [64*64*32*32];
__device__ float g_e [64*64*32*32];
__device__ float g_d1[64*64*64*64];
__device__ float g_d2[64*32*128*128];
__device__ double g_vq_loss;
__device__ double g_recon;

__global__ void k_zero() { g_vq_loss = 0.0; g_recon = 0.0; }

// ---------------- enc conv1: 3->32, k3 s2 p1, 125->63, relu ----------------
__global__ void k_conv1(const float* __restrict__ x, const float* __restrict__ w,
                        const float* __restrict__ b) {
    int idx = blockIdx.x * 256 + threadIdx.x;
    if (idx >= 64*32*63*63) return;
    int ow = idx % 63; int t = idx / 63;
    int oh = t % 63;  t /= 63;
    int co = t % 32;  int n = t / 32;
    float acc = b[co];
    const float* xb = x + n*3*125*125;
    const float* wb = w + co*3*9;
    #pragma unroll
    for (int ci = 0; ci < 3; ci++) {
        #pragma unroll
        for (int kh = 0; kh < 3; kh++) {
            int ih = 2*oh + kh - 1;
            if ((unsigned)ih < 125u) {
                #pragma unroll
                for (int kw = 0; kw < 3; kw++) {
                    int iw = 2*ow + kw - 1;
                    if ((unsigned)iw < 125u)
                        acc += wb[ci*9 + kh*3 + kw] * xb[(ci*125 + ih)*125 + iw];
                }
            }
        }
    }
    g_a1[idx] = fmaxf(acc, 0.f);
}

// ---------------- enc conv2: 32->64, k3 s2 p1, 63->32 ------
// co-pair lanes, 2 adjacent-ow pixels/thread; weights padded for LDS.128
__global__ void __launch_bounds__(256) k_conv2(const float* __restrict__ w,
                                               const float* __restrict__ b) {
    __shared__ float2 wp[32][4][10];     // [ci][jp][tap] padded to 80B rows
    int bid   = blockIdx.x;              // 1024 = 64n * 8cog * 2ohhalf
    int ohh   = bid & 1;
    int cog   = (bid >> 1) & 7;
    int n     = bid >> 4;
    int co0   = cog * 8;
    for (int i = threadIdx.x; i < 32*4*9; i += 256) {
        int t  = i % 9;
        int jp = (i/9) & 3;
        int ci = i / 36;
        wp[ci][jp][t] = make_float2(w[((co0 + 2*jp)    *32 + ci)*9 + t],
                                    w[((co0 + 2*jp + 1)*32 + ci)*9 + t]);
    }
    __syncthreads();
    int q  = threadIdx.x & 15;
    int oh = ohh*16 + (threadIdx.x >> 4);
    u64 accA[4], accB[4];
    #pragma unroll
    for (int jp = 0; jp < 4; jp++) {
        u64 bv = pack2(b[co0+2*jp], b[co0+2*jp+1]);
        accA[jp] = bv; accB[jp] = bv;
    }
    const float* ib = g_a1 + n*32*63*63;
    int iwb = 4*q - 1;
    for (int ci = 0; ci < 32; ci++) {
        u64 col[3][5];
        #pragma unroll
        for (int kh = 0; kh < 3; kh++) {
            int ih = 2*oh + kh - 1;
            bool hok = (unsigned)ih < 63u;
            const float* row = ib + (ci*63 + ih)*63;
            #pragma unroll
            for (int c = 0; c < 5; c++) {
                int iw = iwb + c;
                float v = (hok && (unsigned)iw < 63u) ? row[iw] : 0.f;
                col[kh][c] = bcast2(v);
            }
        }
        #pragma unroll
        for (int jp = 0; jp < 4; jp++) {
            const ulonglong2* Wq = (const ulonglong2*)wp[ci][jp];
            ulonglong2 q0 = Wq[0];             // w0,w1
            ulonglong2 q1 = Wq[1];             // w2,w3
            ulonglong2 q2 = Wq[2];             // w4,w5
            ulonglong2 q3 = Wq[3];             // w6,w7
            u64 w8 = *(const u64*)&wp[ci][jp][8];
            // taps 0..8 map to (kh,kw) = (t/3, t%3)
            fma2(accA[jp], q0.x, col[0][0]); fma2(accB[jp], q0.x, col[0][2]);
            fma2(accA[jp], q0.y, col[0][1]); fma2(accB[jp], q0.y, col[0][3]);
            fma2(accA[jp], q1.x, col[0][2]); fma2(accB[jp], q1.x, col[0][4]);
            fma2(accA[jp], q1.y, col[1][0]); fma2(accB[jp], q1.y, col[1][2]);
            fma2(accA[jp], q2.x, col[1][1]); fma2(accB[jp], q2.x, col[1][3]);
            fma2(accA[jp], q2.y, col[1][2]); fma2(accB[jp], q2.y, col[1][4]);
            fma2(accA[jp], q3.x, col[2][0]); fma2(accB[jp], q3.x, col[2][2]);
            fma2(accA[jp], q3.y, col[2][1]); fma2(accB[jp], q3.y, col[2][3]);
            fma2(accA[jp], w8,   col[2][2]); fma2(accB[jp], w8,   col[2][4]);
        }
    }
    int ohw = oh*32 + 2*q;
    #pragma unroll
    for (int jp = 0; jp < 4; jp++) {
        float2 a = unpack2(accA[jp]);
        float2 c = unpack2(accB[jp]);
        *(float2*)&g_a2[(n*64 + co0 + 2*jp    )*1024 + ohw]
            = make_float2(fmaxf(a.x,0.f), fmaxf(c.x,0.f));
        *(float2*)&g_a2[(n*64 + co0 + 2*jp + 1)*1024 + ohw]
            = make_float2(fmaxf(a.y,0.f), fmaxf(c.y,0.f));
    }
}

// ---------------- enc conv3: 64->64 1x1 (R1 scalar form: best measured) --
__global__ void k_conv3(const float* __restrict__ w, const float* __restrict__ b) {
    __shared__ float ws[16*64];
    int bid  = blockIdx.x;                 // 1024 = 64n * 4cog * 4tile
    int tile = bid & 3;
    int cog  = (bid >> 2) & 3;
    int n    = bid >> 4;
    int co0  = cog * 16;
    for (int i = threadIdx.x; i < 1024; i += 256) ws[i] = w[co0*64 + i];
    __syncthreads();
    int hw = tile*256 + threadIdx.x;
    float acc[16];
    #pragma unroll
    for (int j = 0; j < 16; j++) acc[j] = b[co0 + j];
    const float* ib = g_a2 + n*64*1024;
    for (int ci = 0; ci < 64; ci++) {
        float v = ib[ci*1024 + hw];
        #pragma unroll
        for (int j = 0; j < 16; j++) acc[j] += ws[j*64 + ci] * v;
    }
    #pragma unroll
    for (int j = 0; j < 16; j++) g_z[(n*64 + co0 + j)*1024 + hw] = acc[j];
}

// ---------------- VQ: argmin over 512 codes, 2 codes x even/odd ILP -------
__global__ void k_vq(const float* __restrict__ codebook) {
    __shared__ float4 cbs[128][16];
    __shared__ float  cns[128];
    __shared__ float  wsum[8];
    int n  = blockIdx.x * 256 + threadIdx.x;    // exact: 256 blocks
    int bb = n >> 10;
    int hw = n & 1023;
    const float* zb = g_z + bb*65536 + hw;
    float zv[64];
    #pragma unroll
    for (int d = 0; d < 64; d++) zv[d] = zb[d*1024];
    u64 zp[32];
    #pragma unroll
    for (int q = 0; q < 32; q++) zp[q] = pack2(zv[2*q], zv[2*q+1]);
    float best = 3.0e38f; int bidx = 0;
    for (int c = 0; c < 4; c++) {
        __syncthreads();
        const float4* src = (const float4*)(codebook + c*128*64);
        for (int i = threadIdx.x; i < 2048; i += 256)
            ((float4*)cbs)[i] = src[i];
        __syncthreads();
        if (threadIdx.x < 128) {
            const float* cc = (const float*)cbs[threadIdx.x];
            float s = 0.f;
            #pragma unroll
            for (int d = 0; d < 64; d++) s += cc[d]*cc[d];
            cns[threadIdx.x] = s;
        }
        __syncthreads();
        for (int k = 0; k < 128; k += 2) {
            const ulonglong2* ck0 = (const ulonglong2*)cbs[k];
            const ulonglong2* ck1 = (const ulonglong2*)cbs[k+1];
            u64 d0e = 0ull, d0o = 0ull, d1e = 0ull, d1o = 0ull;
            #pragma unroll
            for (int q2 = 0; q2 < 16; q2++) {
                ulonglong2 c0 = ck0[q2];
                ulonglong2 c1 = ck1[q2];
                fma2(d0e, c0.x, zp[2*q2]);
                fma2(d0o, c0.y, zp[2*q2+1]);
                fma2(d1e, c1.x, zp[2*q2]);
                fma2(d1o, c1.y, zp[2*q2+1]);
            }
            float2 a0 = unpack2(d0e), b0 = unpack2(d0o);
            float2 a1 = unpack2(d1e), b1 = unpack2(d1o);
            float dist0 = cns[k]   - 2.f*(a0.x + a0.y + b0.x + b0.y);
            float dist1 = cns[k+1] - 2.f*(a1.x + a1.y + b1.x + b1.y);
            if (dist0 < best) { best = dist0; bidx = c*128 + k; }
            if (dist1 < best) { best = dist1; bidx = c*128 + k + 1; }
        }
    }
    const float* cbest = codebook + bidx*64;
    float* eb = g_e + bb*65536 + hw;
    float ls = 0.f;
    #pragma unroll
    for (int d = 0; d < 64; d++) {
        float qv = cbest[d];
        float df = qv - zv[d];
        ls += df*df;
        eb[d*1024] = qv;
    }
    #pragma unroll
    for (int off = 16; off; off >>= 1) ls += __shfl_down_sync(0xffffffffu, ls, off);
    if ((threadIdx.x & 31) == 0) wsum[threadIdx.x >> 5] = ls;
    __syncthreads();
    if (threadIdx.x == 0) {
        float s = 0.f;
        #pragma unroll
        for (int i = 0; i < 8; i++) s += wsum[i];
        atomicAdd(&g_vq_loss, (double)s);
    }
}

// =====================================================================
// decT core: co-pair lanes, 2 pixels/thread (rows m, m+16),
// weight taps read via LDS.128 (padded smem rows).
// tap layout per jp: [w0,w1][w2,w3][w4,w5][w6,w7][w8,pad]
// =====================================================================
template<int S>
__device__ __forceinline__ void dec_core(
    const float* __restrict__ ib, const float* __restrict__ w, int CO,
    const float* __restrict__ b, float* __restrict__ ob,
    int co0, int m0, int l0)
{
    __shared__ float2 wp[64][4][10];     // 20KB, 80B per jp row (16B aligned)
    int tid = threadIdx.x;
    for (int i = tid; i < 64*4*9; i += 256) {
        int t  = i % 9;
        int jp = (i/9) & 3;
        int ci = i / 36;
        wp[ci][jp][t] = make_float2(w[(ci*CO + co0 + 2*jp    )*9 + t],
                                    w[(ci*CO + co0 + 2*jp + 1)*9 + t]);
    }
    __syncthreads();

    int dl = tid & 15, dm = tid >> 4;
    int l  = l0 + dl;
    int mA = m0 + dm;
    int mB = mA + 16;
    u64 aA[4][4], aB[4][4];
    #pragma unroll
    for (int jp = 0; jp < 4; jp++) {
        u64 bv = pack2(b[co0+2*jp], b[co0+2*jp+1]);
        #pragma unroll
        for (int p = 0; p < 4; p++) { aA[jp][p] = bv; aB[jp][p] = bv; }
    }
    bool lok  = (l  + 1) < S;
    bool mAok = (mA + 1) < S;
    bool mBok = (mB + 1) < S;
    const float* pA0 = ib + mA*S + l;
    const float* pB0 = ib + mB*S + l;
    for (int ci = 0; ci < 64; ci++) {
        const float* pA = pA0 + ci*S*S;
        const float* pB = pB0 + ci*S*S;
        u64 A00 = bcast2(pA[0]);
        u64 A01 = bcast2(lok ? pA[1] : 0.f);
        u64 A10 = bcast2(mAok ? pA[S] : 0.f);
        u64 A11 = bcast2((mAok && lok) ? pA[S+1] : 0.f);
        u64 B00 = bcast2(pB[0]);
        u64 B01 = bcast2(lok ? pB[1] : 0.f);
        u64 B10 = bcast2(mBok ? pB[S] : 0.f);
        u64 B11 = bcast2((mBok && lok) ? pB[S+1] : 0.f);
        #pragma unroll
        for (int jp = 0; jp < 4; jp++) {
            const ulonglong2* Wq = (const ulonglong2*)wp[ci][jp];
            ulonglong2 q0 = Wq[0];             // w0,w1
            ulonglong2 q1 = Wq[1];             // w2,w3
            ulonglong2 q2 = Wq[2];             // w4,w5
            ulonglong2 q3 = Wq[3];             // w6,w7
            u64 w8 = *(const u64*)&wp[ci][jp][8];
            // pos0 += w4*i00
            fma2(aA[jp][0], q2.x, A00); fma2(aB[jp][0], q2.x, B00);
            // pos1 += w3*i01 + w5*i00
            fma2(aA[jp][1], q1.y, A01); fma2(aB[jp][1], q1.y, B01);
            fma2(aA[jp][1], q2.y, A00); fma2(aB[jp][1], q2.y, B00);
            // pos2 += w1*i10 + w7*i00
            fma2(aA[jp][2], q0.y, A10); fma2(aB[jp][2], q0.y, B10);
            fma2(aA[jp][2], q3.y, A00); fma2(aB[jp][2], q3.y, B00);
            // pos3 += w0*i11 + w2*i10 + w6*i01 + w8*i00
            fma2(aA[jp][3], q0.x, A11); fma2(aB[jp][3], q0.x, B11);
            fma2(aA[jp][3], q1.x, A10); fma2(aB[jp][3], q1.x, B10);
            fma2(aA[jp][3], q3.x, A01); fma2(aB[jp][3], q3.x, B01);
            fma2(aA[jp][3], w8,   A00); fma2(aB[jp][3], w8,   B00);
        }
    }
    const int O = 2*S;
    #pragma unroll
    for (int jp = 0; jp < 4; jp++) {
        float2 a0 = unpack2(aA[jp][0]);
        float2 a1 = unpack2(aA[jp][1]);
        float2 a2 = unpack2(aA[jp][2]);
        float2 a3 = unpack2(aA[jp][3]);
        float* o0 = ob + (2*jp)*O*O + (2*mA)*O + 2*l;
        float* o1 = o0 + O*O;
        *(float2*)(o0)     = make_float2(fmaxf(a0.x,0.f), fmaxf(a1.x,0.f));
        *(float2*)(o0 + O) = make_float2(fmaxf(a2.x,0.f), fmaxf(a3.x,0.f));
        *(float2*)(o1)     = make_float2(fmaxf(a0.y,0.f), fmaxf(a1.y,0.f));
        *(float2*)(o1 + O) = make_float2(fmaxf(a2.y,0.f), fmaxf(a3.y,0.f));
        float2 b0 = unpack2(aB[jp][0]);
        float2 b1 = unpack2(aB[jp][1]);
        float2 b2 = unpack2(aB[jp][2]);
        float2 b3 = unpack2(aB[jp][3]);
        float* q0 = ob + (2*jp)*O*O + (2*mB)*O + 2*l;
        float* q1 = q0 + O*O;
        *(float2*)(q0)     = make_float2(fmaxf(b0.x,0.f), fmaxf(b1.x,0.f));
        *(float2*)(q0 + O) = make_float2(fmaxf(b2.x,0.f), fmaxf(b3.x,0.f));
        *(float2*)(q1)     = make_float2(fmaxf(b0.y,0.f), fmaxf(b1.y,0.f));
        *(float2*)(q1 + O) = make_float2(fmaxf(b2.y,0.f), fmaxf(b3.y,0.f));
    }
}

// decT1: 64->64, 32x32 -> 64x64
__global__ void __launch_bounds__(256, 2) k_dec1(const float* __restrict__ w,
                                                 const float* __restrict__ b) {
    int bid   = blockIdx.x;            // 1024 = 64n * 8cog * 2lhalf
    int lhalf = bid & 1;
    int cog   = (bid >> 1) & 7;
    int n     = bid >> 4;
    int co0   = cog * 8;
    dec_core<32>(g_e + n*64*1024, w, 64, b, g_d1 + (n*64 + co0)*4096,
                 co0, 0, lhalf*16);
}

// decT2: 64->32, 64x64 -> 128x128
__global__ void __launch_bounds__(256, 2) k_dec2(const float* __restrict__ w,
                                                 const float* __restrict__ b) {
    int bid  = blockIdx.x;             // 2048 = 64n * 4cog * 8tile
    int t    = bid & 7;
    int l0   = (t & 3) * 16;
    int m0   = (t >> 2) * 32;
    int cog  = (bid >> 3) & 3;
    int n    = bid >> 5;
    int co0  = cog * 8;
    dec_core<64>(g_d1 + n*64*4096, w, 32, b, g_d2 + (n*32 + co0)*16384,
                 co0, m0, l0);
}

// ---------------- decT3: 32->3, k2 s1 p2, 128->125 + recon loss -------------
__global__ void k_dec3(const float* __restrict__ w, const float* __restrict__ bs,
                       const float* __restrict__ x, float* __restrict__ out) {
    __shared__ float ws[384];          // per-ci 12 floats, 16B aligned rows
    __shared__ float wsum[8];
    for (int i = threadIdx.x; i < 384; i += 256) ws[i] = w[i];
    __syncthreads();
    int idx = blockIdx.x * 256 + threadIdx.x;
    float lsum = 0.f;
    if (idx < 1000000) {
        int ow = idx % 125; int t = idx / 125;
        int oh = t % 125;   int n = t / 125;
        u64 accA[3], accB[3];
        #pragma unroll
        for (int co = 0; co < 3; co++) { accA[co] = 0ull; accB[co] = 0ull; }
        const float* ib = g_d2 + n*32*16384;
        const float* p  = ib + (oh+1)*128 + (ow+1);
        for (int ci = 0; ci < 32; ci++) {
            const float* q = p + ci*16384;
            u64 A = pack2(q[129], q[128]);
            u64 B = pack2(q[1],   q[0]);
            const ulonglong2* Wq = (const ulonglong2*)(ws + ci*12);
            ulonglong2 v0 = Wq[0];   // co0: WA,WB
            ulonglong2 v1 = Wq[1];   // co1: WA,WB
            ulonglong2 v2 = Wq[2];   // co2: WA,WB
            fma2(accA[0], v0.x, A); fma2(accB[0], v0.y, B);
            fma2(accA[1], v1.x, A); fma2(accB[1], v1.y, B);
            fma2(accA[2], v2.x, A); fma2(accB[2], v2.y, B);
        }
        #pragma unroll
        for (int co = 0; co < 3; co++) {
            float2 a = unpack2(accA[co]);
            float2 c = unpack2(accB[co]);
            float v = bs[co] + a.x + a.y + c.x + c.y;
            int oi = ((n*3 + co)*125 + oh)*125 + ow;
            out[oi] = v;
            float d = v - x[oi];
            lsum += d*d;
        }
    }
    #pragma unroll
    for (int off = 16; off; off >>= 1) lsum += __shfl_down_sync(0xffffffffu, lsum, off);
    if ((threadIdx.x & 31) == 0) wsum[threadIdx.x >> 5] = lsum;
    __syncthreads();
    if (threadIdx.x == 0) {
        float s = 0.f;
        #pragma unroll
        for (int i = 0; i < 8; i++) s += wsum[i];
        atomicAdd(&g_recon, (double)s);
    }
}

// ---------------- finalize ----------------
__global__ void k_final(float* __restrict__ out) {
    double mse = g_vq_loss / (65536.0 * 64.0);
    float eq  = (float)(1.25 * mse);
    float rec = (float)g_recon;
    out[0] = eq + rec;
    out[1] = eq;
    out[2] = rec;
}

extern "C" void kernel_launch(void* const* d_in, const int* in_sizes, int n_in,
                              void* d_out, int out_size) {
    const float* x   = (const float*)d_in[0];
    const float* ew1 = (const float*)d_in[1];
    const float* eb1 = (const float*)d_in[2];
    const float* ew2 = (const float*)d_in[3];
    const float* eb2 = (const float*)d_in[4];
    const float* ew3 = (const float*)d_in[5];
    const float* eb3 = (const float*)d_in[6];
    const float* cb  = (const float*)d_in[7];
    const float* dw1 = (const float*)d_in[8];
    const float* db1 = (const float*)d_in[9];
    const float* dw2 = (const float*)d_in[10];
    const float* db2 = (const float*)d_in[11];
    const float* dw3 = (const float*)d_in[12];
    const float* db3 = (const float*)d_in[13];
    float* out = (float*)d_out;

    k_zero <<<1, 1>>>();
    k_conv1<<<(64*32*63*63 + 255)/256, 256>>>(x, ew1, eb1);
    k_conv2<<<1024, 256>>>(ew2, eb2);
    k_conv3<<<1024, 256>>>(ew3, eb3);
    k_vq   <<<256, 256>>>(cb);
    k_dec1 <<<1024, 256>>>(dw1, db1);
    k_dec2 <<<2048, 256>>>(dw2, db2);
    k_dec3 <<<3907, 256>>>(dw3, db3, x, out + 3);
    k_final<<<1, 1>>>(out);
}

// round 8
// speedup vs baseline: 1.2892x; 1.0970x over previous
#include <cuda_runtime.h>
#include <cuda_bf16.h>

typedef unsigned long long u64;

// ---------------- f32x2 packed-math helpers (sm_103a FFMA2) ----------------
__device__ __forceinline__ u64 pack2(float lo, float hi) {
    u64 r;
    asm("mov.b64 %0, {%1, %2};" : "=l"(r)
        : "r"(__float_as_uint(lo)), "r"(__float_as_uint(hi)));
    return r;
}
__device__ __forceinline__ u64 bcast2(float v) { return pack2(v, v); }
__device__ __forceinline__ void fma2(u64& d, u64 a, u64 b) {
    asm("fma.rn.f32x2 %0, %1, %2, %0;" : "+l"(d) : "l"(a), "l"(b));
}
__device__ __forceinline__ float2 unpack2(u64 v) {
    unsigned lo, hi;
    asm("mov.b64 {%0, %1}, %2;" : "=r"(lo), "=r"(hi) : "l"(v));
    return make_float2(__uint_as_float(lo), __uint_as_float(hi));
}

// ---------------- scratch (allocation-free: __device__ globals) ----------------
__device__ float g_a1[64*32*63*63];
__device__ float g_a2[64*64*32*32];
__device__ float g_z [64*64*32*32];
__device__ float g_e [64*64*32*32];
__device__ float g_d1[64*64*64*64];
__device__ float g_d2[64*32*128*128];
__device__ double g_vq_loss;
__device__ double g_recon;

__global__ void k_zero() { g_vq_loss = 0.0; g_recon = 0.0; }

// ---------------- enc conv1: 3->32, k3 s2 p1, 125->63, relu ----------------
// co-block of 16 (8 pairs) per thread, 2 adjacent-ow pixels share input cols.
// grid: 64n * 2cog * 8 inner-blocks of 256 (2016 pair-slots per (n,cog))
__global__ void __launch_bounds__(256) k_conv1(const float* __restrict__ x,
                                               const float* __restrict__ w,
                                               const float* __restrict__ b) {
    __shared__ u64 wp[3*9*8];            // [ci][t][jq-pair] co-pair packed
    int bid  = blockIdx.x;               // 1024 = 64n * 2cog * 8ib
    int ib   = bid & 7;
    int cog  = (bid >> 3) & 1;
    int n    = bid >> 4;
    int co0  = cog * 16;
    for (int i = threadIdx.x; i < 216; i += 256) {
        int jq = i & 7;
        int t  = (i >> 3) % 9;
        int ci = i / 72;
        int co = co0 + 2*jq;
        wp[(ci*9 + t)*8 + jq] = pack2(w[co*27 + ci*9 + t],
                                      w[(co+1)*27 + ci*9 + t]);
    }
    __syncthreads();
    int r2 = ib*256 + threadIdx.x;       // 0..2047, valid < 2016
    if (r2 >= 2016) return;
    int qp = r2 & 31;                    // ow pair index: ow0 = 2*qp
    int oh = r2 >> 5;                    // 0..62
    int ow0 = 2*qp;
    bool hasB = (qp != 31);              // ow1 = ow0+1 <= 62
    u64 accA[8], accB[8];
    #pragma unroll
    for (int jq = 0; jq < 8; jq++) {
        u64 bv = pack2(b[co0+2*jq], b[co0+2*jq+1]);
        accA[jq] = bv; accB[jq] = bv;
    }
    const float* xb = x + n*3*125*125;
    int iwb = 4*qp - 1;
    #pragma unroll
    for (int ci = 0; ci < 3; ci++) {
        u64 col[3][5];
        #pragma unroll
        for (int kh = 0; kh < 3; kh++) {
            int ihh = 2*oh + kh - 1;
            bool hok = (unsigned)ihh < 125u;
            const float* row = xb + (ci*125 + ihh)*125;
            #pragma unroll
            for (int c = 0; c < 5; c++) {
                int iw = iwb + c;
                float v = (hok && (unsigned)iw < 125u) ? row[iw] : 0.f;
                col[kh][c] = bcast2(v);
            }
        }
        #pragma unroll
        for (int kh = 0; kh < 3; kh++) {
            #pragma unroll
            for (int kw = 0; kw < 3; kw++) {
                int t = kh*3 + kw;
                const ulonglong2* Wq = (const ulonglong2*)&wp[(ci*9 + t)*8];
                u64 cA = col[kh][kw];
                u64 cB = col[kh][kw+2];
                #pragma unroll
                for (int h = 0; h < 4; h++) {
                    ulonglong2 W = Wq[h];
                    fma2(accA[2*h],   W.x, cA);
                    fma2(accA[2*h+1], W.y, cA);
                    fma2(accB[2*h],   W.x, cB);
                    fma2(accB[2*h+1], W.y, cB);
                }
            }
        }
    }
    float* ob = g_a1 + ((n*32 + co0)*63 + oh)*63 + ow0;
    #pragma unroll
    for (int jq = 0; jq < 8; jq++) {
        float2 a = unpack2(accA[jq]);
        float2 c = unpack2(accB[jq]);
        float* o0 = ob + (2*jq)*3969;    // 63*63
        float* o1 = o0 + 3969;
        o0[0] = fmaxf(a.x, 0.f);
        o1[0] = fmaxf(a.y, 0.f);
        if (hasB) {
            o0[1] = fmaxf(c.x, 0.f);
            o1[1] = fmaxf(c.y, 0.f);
        }
    }
}

// ---------------- enc conv2: 32->64, k3 s2 p1, 63->32 ------
__global__ void __launch_bounds__(256) k_conv2(const float* __restrict__ w,
                                               const float* __restrict__ b) {
    __shared__ float2 wp[32][4][10];     // [ci][jp][tap] padded to 80B rows
    int bid   = blockIdx.x;              // 1024 = 64n * 8cog * 2ohhalf
    int ohh   = bid & 1;
    int cog   = (bid >> 1) & 7;
    int n     = bid >> 4;
    int co0   = cog * 8;
    for (int i = threadIdx.x; i < 32*4*9; i += 256) {
        int t  = i % 9;
        int jp = (i/9) & 3;
        int ci = i / 36;
        wp[ci][jp][t] = make_float2(w[((co0 + 2*jp)    *32 + ci)*9 + t],
                                    w[((co0 + 2*jp + 1)*32 + ci)*9 + t]);
    }
    __syncthreads();
    int q  = threadIdx.x & 15;
    int oh = ohh*16 + (threadIdx.x >> 4);
    u64 accA[4], accB[4];
    #pragma unroll
    for (int jp = 0; jp < 4; jp++) {
        u64 bv = pack2(b[co0+2*jp], b[co0+2*jp+1]);
        accA[jp] = bv; accB[jp] = bv;
    }
    const float* ib = g_a1 + n*32*63*63;
    int iwb = 4*q - 1;
    for (int ci = 0; ci < 32; ci++) {
        u64 col[3][5];
        #pragma unroll
        for (int kh = 0; kh < 3; kh++) {
            int ih = 2*oh + kh - 1;
            bool hok = (unsigned)ih < 63u;
            const float* row = ib + (ci*63 + ih)*63;
            #pragma unroll
            for (int c = 0; c < 5; c++) {
                int iw = iwb + c;
                float v = (hok && (unsigned)iw < 63u) ? row[iw] : 0.f;
                col[kh][c] = bcast2(v);
            }
        }
        #pragma unroll
        for (int jp = 0; jp < 4; jp++) {
            const ulonglong2* Wq = (const ulonglong2*)wp[ci][jp];
            ulonglong2 q0 = Wq[0];
            ulonglong2 q1 = Wq[1];
            ulonglong2 q2 = Wq[2];
            ulonglong2 q3 = Wq[3];
            u64 w8 = *(const u64*)&wp[ci][jp][8];
            fma2(accA[jp], q0.x, col[0][0]); fma2(accB[jp], q0.x, col[0][2]);
            fma2(accA[jp], q0.y, col[0][1]); fma2(accB[jp], q0.y, col[0][3]);
            fma2(accA[jp], q1.x, col[0][2]); fma2(accB[jp], q1.x, col[0][4]);
            fma2(accA[jp], q1.y, col[1][0]); fma2(accB[jp], q1.y, col[1][2]);
            fma2(accA[jp], q2.x, col[1][1]); fma2(accB[jp], q2.x, col[1][3]);
            fma2(accA[jp], q2.y, col[1][2]); fma2(accB[jp], q2.y, col[1][4]);
            fma2(accA[jp], q3.x, col[2][0]); fma2(accB[jp], q3.x, col[2][2]);
            fma2(accA[jp], q3.y, col[2][1]); fma2(accB[jp], q3.y, col[2][3]);
            fma2(accA[jp], w8,   col[2][2]); fma2(accB[jp], w8,   col[2][4]);
        }
    }
    int ohw = oh*32 + 2*q;
    #pragma unroll
    for (int jp = 0; jp < 4; jp++) {
        float2 a = unpack2(accA[jp]);
        float2 c = unpack2(accB[jp]);
        *(float2*)&g_a2[(n*64 + co0 + 2*jp    )*1024 + ohw]
            = make_float2(fmaxf(a.x,0.f), fmaxf(c.x,0.f));
        *(float2*)&g_a2[(n*64 + co0 + 2*jp + 1)*1024 + ohw]
            = make_float2(fmaxf(a.y,0.f), fmaxf(c.y,0.f));
    }
}

// ---------------- enc conv3: 64->64 1x1 (R1 scalar form: best measured) --
__global__ void k_conv3(const float* __restrict__ w, const float* __restrict__ b) {
    __shared__ float ws[16*64];
    int bid  = blockIdx.x;                 // 1024 = 64n * 4cog * 4tile
    int tile = bid & 3;
    int cog  = (bid >> 2) & 3;
    int n    = bid >> 4;
    int co0  = cog * 16;
    for (int i = threadIdx.x; i < 1024; i += 256) ws[i] = w[co0*64 + i];
    __syncthreads();
    int hw = tile*256 + threadIdx.x;
    float acc[16];
    #pragma unroll
    for (int j = 0; j < 16; j++) acc[j] = b[co0 + j];
    const float* ib = g_a2 + n*64*1024;
    for (int ci = 0; ci < 64; ci++) {
        float v = ib[ci*1024 + hw];
        #pragma unroll
        for (int j = 0; j < 16; j++) acc[j] += ws[j*64 + ci] * v;
    }
    #pragma unroll
    for (int j = 0; j < 16; j++) g_z[(n*64 + co0 + j)*1024 + hw] = acc[j];
}

// ---------------- VQ: argmin over 512 codes, 2 codes x even/odd ILP -------
__global__ void k_vq(const float* __restrict__ codebook) {
    __shared__ float4 cbs[128][16];
    __shared__ float  cns[128];
    __shared__ float  wsum[8];
    int n  = blockIdx.x * 256 + threadIdx.x;    // exact: 256 blocks
    int bb = n >> 10;
    int hw = n & 1023;
    const float* zb = g_z + bb*65536 + hw;
    float zv[64];
    #pragma unroll
    for (int d = 0; d < 64; d++) zv[d] = zb[d*1024];
    u64 zp[32];
    #pragma unroll
    for (int q = 0; q < 32; q++) zp[q] = pack2(zv[2*q], zv[2*q+1]);
    float best = 3.0e38f; int bidx = 0;
    for (int c = 0; c < 4; c++) {
        __syncthreads();
        const float4* src = (const float4*)(codebook + c*128*64);
        for (int i = threadIdx.x; i < 2048; i += 256)
            ((float4*)cbs)[i] = src[i];
        __syncthreads();
        if (threadIdx.x < 128) {
            const float* cc = (const float*)cbs[threadIdx.x];
            float s = 0.f;
            #pragma unroll
            for (int d = 0; d < 64; d++) s += cc[d]*cc[d];
            cns[threadIdx.x] = s;
        }
        __syncthreads();
        for (int k = 0; k < 128; k += 2) {
            const ulonglong2* ck0 = (const ulonglong2*)cbs[k];
            const ulonglong2* ck1 = (const ulonglong2*)cbs[k+1];
            u64 d0e = 0ull, d0o = 0ull, d1e = 0ull, d1o = 0ull;
            #pragma unroll
            for (int q2 = 0; q2 < 16; q2++) {
                ulonglong2 c0 = ck0[q2];
                ulonglong2 c1 = ck1[q2];
                fma2(d0e, c0.x, zp[2*q2]);
                fma2(d0o, c0.y, zp[2*q2+1]);
                fma2(d1e, c1.x, zp[2*q2]);
                fma2(d1o, c1.y, zp[2*q2+1]);
            }
            float2 a0 = unpack2(d0e), b0 = unpack2(d0o);
            float2 a1 = unpack2(d1e), b1 = unpack2(d1o);
            float dist0 = cns[k]   - 2.f*(a0.x + a0.y + b0.x + b0.y);
            float dist1 = cns[k+1] - 2.f*(a1.x + a1.y + b1.x + b1.y);
            if (dist0 < best) { best = dist0; bidx = c*128 + k; }
            if (dist1 < best) { best = dist1; bidx = c*128 + k + 1; }
        }
    }
    const float* cbest = codebook + bidx*64;
    float* eb = g_e + bb*65536 + hw;
    float ls = 0.f;
    #pragma unroll
    for (int d = 0; d < 64; d++) {
        float qv = cbest[d];
        float df = qv - zv[d];
        ls += df*df;
        eb[d*1024] = qv;
    }
    #pragma unroll
    for (int off = 16; off; off >>= 1) ls += __shfl_down_sync(0xffffffffu, ls, off);
    if ((threadIdx.x & 31) == 0) wsum[threadIdx.x >> 5] = ls;
    __syncthreads();
    if (threadIdx.x == 0) {
        float s = 0.f;
        #pragma unroll
        for (int i = 0; i < 8; i++) s += wsum[i];
        atomicAdd(&g_vq_loss, (double)s);
    }
}

// =====================================================================
// decT core: co-pair lanes, 2 pixels/thread, LDS.128 weight reads
// =====================================================================
template<int S>
__device__ __forceinline__ void dec_core(
    const float* __restrict__ ib, const float* __restrict__ w, int CO,
    const float* __restrict__ b, float* __restrict__ ob,
    int co0, int m0, int l0)
{
    __shared__ float2 wp[64][4][10];
    int tid = threadIdx.x;
    for (int i = tid; i < 64*4*9; i += 256) {
        int t  = i % 9;
        int jp = (i/9) & 3;
        int ci = i / 36;
        wp[ci][jp][t] = make_float2(w[(ci*CO + co0 + 2*jp    )*9 + t],
                                    w[(ci*CO + co0 + 2*jp + 1)*9 + t]);
    }
    __syncthreads();

    int dl = tid & 15, dm = tid >> 4;
    int l  = l0 + dl;
    int mA = m0 + dm;
    int mB = mA + 16;
    u64 aA[4][4], aB[4][4];
    #pragma unroll
    for (int jp = 0; jp < 4; jp++) {
        u64 bv = pack2(b[co0+2*jp], b[co0+2*jp+1]);
        #pragma unroll
        for (int p = 0; p < 4; p++) { aA[jp][p] = bv; aB[jp][p] = bv; }
    }
    bool lok  = (l  + 1) < S;
    bool mAok = (mA + 1) < S;
    bool mBok = (mB + 1) < S;
    const float* pA0 = ib + mA*S + l;
    const float* pB0 = ib + mB*S + l;
    for (int ci = 0; ci < 64; ci++) {
        const float* pA = pA0 + ci*S*S;
        const float* pB = pB0 + ci*S*S;
        u64 A00 = bcast2(pA[0]);
        u64 A01 = bcast2(lok ? pA[1] : 0.f);
        u64 A10 = bcast2(mAok ? pA[S] : 0.f);
        u64 A11 = bcast2((mAok && lok) ? pA[S+1] : 0.f);
        u64 B00 = bcast2(pB[0]);
        u64 B01 = bcast2(lok ? pB[1] : 0.f);
        u64 B10 = bcast2(mBok ? pB[S] : 0.f);
        u64 B11 = bcast2((mBok && lok) ? pB[S+1] : 0.f);
        #pragma unroll
        for (int jp = 0; jp < 4; jp++) {
            const ulonglong2* Wq = (const ulonglong2*)wp[ci][jp];
            ulonglong2 q0 = Wq[0];
            ulonglong2 q1 = Wq[1];
            ulonglong2 q2 = Wq[2];
            ulonglong2 q3 = Wq[3];
            u64 w8 = *(const u64*)&wp[ci][jp][8];
            fma2(aA[jp][0], q2.x, A00); fma2(aB[jp][0], q2.x, B00);
            fma2(aA[jp][1], q1.y, A01); fma2(aB[jp][1], q1.y, B01);
            fma2(aA[jp][1], q2.y, A00); fma2(aB[jp][1], q2.y, B00);
            fma2(aA[jp][2], q0.y, A10); fma2(aB[jp][2], q0.y, B10);
            fma2(aA[jp][2], q3.y, A00); fma2(aB[jp][2], q3.y, B00);
            fma2(aA[jp][3], q0.x, A11); fma2(aB[jp][3], q0.x, B11);
            fma2(aA[jp][3], q1.x, A10); fma2(aB[jp][3], q1.x, B10);
            fma2(aA[jp][3], q3.x, A01); fma2(aB[jp][3], q3.x, B01);
            fma2(aA[jp][3], w8,   A00); fma2(aB[jp][3], w8,   B00);
        }
    }
    const int O = 2*S;
    #pragma unroll
    for (int jp = 0; jp < 4; jp++) {
        float2 a0 = unpack2(aA[jp][0]);
        float2 a1 = unpack2(aA[jp][1]);
        float2 a2 = unpack2(aA[jp][2]);
        float2 a3 = unpack2(aA[jp][3]);
        float* o0 = ob + (2*jp)*O*O + (2*mA)*O + 2*l;
        float* o1 = o0 + O*O;
        *(float2*)(o0)     = make_float2(fmaxf(a0.x,0.f), fmaxf(a1.x,0.f));
        *(float2*)(o0 + O) = make_float2(fmaxf(a2.x,0.f), fmaxf(a3.x,0.f));
        *(float2*)(o1)     = make_float2(fmaxf(a0.y,0.f), fmaxf(a1.y,0.f));
        *(float2*)(o1 + O) = make_float2(fmaxf(a2.y,0.f), fmaxf(a3.y,0.f));
        float2 b0 = unpack2(aB[jp][0]);
        float2 b1 = unpack2(aB[jp][1]);
        float2 b2 = unpack2(aB[jp][2]);
        float2 b3 = unpack2(aB[jp][3]);
        float* q0 = ob + (2*jp)*O*O + (2*mB)*O + 2*l;
        float* q1 = q0 + O*O;
        *(float2*)(q0)     = make_float2(fmaxf(b0.x,0.f), fmaxf(b1.x,0.f));
        *(float2*)(q0 + O) = make_float2(fmaxf(b2.x,0.f), fmaxf(b3.x,0.f));
        *(float2*)(q1)     = make_float2(fmaxf(b0.y,0.f), fmaxf(b1.y,0.f));
        *(float2*)(q1 + O) = make_float2(fmaxf(b2.y,0.f), fmaxf(b3.y,0.f));
    }
}

// decT1: 64->64, 32x32 -> 64x64
__global__ void __launch_bounds__(256, 2) k_dec1(const float* __restrict__ w,
                                                 const float* __restrict__ b) {
    int bid   = blockIdx.x;            // 1024 = 64n * 8cog * 2lhalf
    int lhalf = bid & 1;
    int cog   = (bid >> 1) & 7;
    int n     = bid >> 4;
    int co0   = cog * 8;
    dec_core<32>(g_e + n*64*1024, w, 64, b, g_d1 + (n*64 + co0)*4096,
                 co0, 0, lhalf*16);
}

// decT2: 64->32, 64x64 -> 128x128
__global__ void __launch_bounds__(256, 2) k_dec2(const float* __restrict__ w,
                                                 const float* __restrict__ b) {
    int bid  = blockIdx.x;             // 2048 = 64n * 4cog * 8tile
    int t    = bid & 7;
    int l0   = (t & 3) * 16;
    int m0   = (t >> 2) * 32;
    int cog  = (bid >> 3) & 3;
    int n    = bid >> 5;
    int co0  = cog * 8;
    dec_core<64>(g_d1 + n*64*4096, w, 32, b, g_d2 + (n*32 + co0)*16384,
                 co0, m0, l0);
}

// ---------------- decT3: 32->3, k2 s1 p2, 128->125 + recon loss -------------
__global__ void k_dec3(const float* __restrict__ w, const float* __restrict__ bs,
                       const float* __restrict__ x, float* __restrict__ out) {
    __shared__ float ws[384];
    __shared__ float wsum[8];
    for (int i = threadIdx.x; i < 384; i += 256) ws[i] = w[i];
    __syncthreads();
    int idx = blockIdx.x * 256 + threadIdx.x;
    float lsum = 0.f;
    if (idx < 1000000) {
        int ow = idx % 125; int t = idx / 125;
        int oh = t % 125;   int n = t / 125;
        u64 accA[3], accB[3];
        #pragma unroll
        for (int co = 0; co < 3; co++) { accA[co] = 0ull; accB[co] = 0ull; }
        const float* ib = g_d2 + n*32*16384;
        const float* p  = ib + (oh+1)*128 + (ow+1);
        for (int ci = 0; ci < 32; ci++) {
            const float* q = p + ci*16384;
            u64 A = pack2(q[129], q[128]);
            u64 B = pack2(q[1],   q[0]);
            const ulonglong2* Wq = (const ulonglong2*)(ws + ci*12);
            ulonglong2 v0 = Wq[0];
            ulonglong2 v1 = Wq[1];
            ulonglong2 v2 = Wq[2];
            fma2(accA[0], v0.x, A); fma2(accB[0], v0.y, B);
            fma2(accA[1], v1.x, A); fma2(accB[1], v1.y, B);
            fma2(accA[2], v2.x, A); fma2(accB[2], v2.y, B);
        }
        #pragma unroll
        for (int co = 0; co < 3; co++) {
            float2 a = unpack2(accA[co]);
            float2 c = unpack2(accB[co]);
            float v = bs[co] + a.x + a.y + c.x + c.y;
            int oi = ((n*3 + co)*125 + oh)*125 + ow;
            out[oi] = v;
            float d = v - x[oi];
            lsum += d*d;
        }
    }
    #pragma unroll
    for (int off = 16; off; off >>= 1) lsum += __shfl_down_sync(0xffffffffu, lsum, off);
    if ((threadIdx.x & 31) == 0) wsum[threadIdx.x >> 5] = lsum;
    __syncthreads();
    if (threadIdx.x == 0) {
        float s = 0.f;
        #pragma unroll
        for (int i = 0; i < 8; i++) s += wsum[i];
        atomicAdd(&g_recon, (double)s);
    }
}

// ---------------- finalize ----------------
__global__ void k_final(float* __restrict__ out) {
    double mse = g_vq_loss / (65536.0 * 64.0);
    float eq  = (float)(1.25 * mse);
    float rec = (float)g_recon;
    out[0] = eq + rec;
    out[1] = eq;
    out[2] = rec;
}

extern "C" void kernel_launch(void* const* d_in, const int* in_sizes, int n_in,
                              void* d_out, int out_size) {
    const float* x   = (const float*)d_in[0];
    const float* ew1 = (const float*)d_in[1];
    const float* eb1 = (const float*)d_in[2];
    const float* ew2 = (const float*)d_in[3];
    const float* eb2 = (const float*)d_in[4];
    const float* ew3 = (const float*)d_in[5];
    const float* eb3 = (const float*)d_in[6];
    const float* cb  = (const float*)d_in[7];
    const float* dw1 = (const float*)d_in[8];
    const float* db1 = (const float*)d_in[9];
    const float* dw2 = (const float*)d_in[10];
    const float* db2 = (const float*)d_in[11];
    const float* dw3 = (const float*)d_in[12];
    const float* db3 = (const float*)d_in[13];
    float* out = (float*)d_out;

    k_zero <<<1, 1>>>();
    k_conv1<<<1024, 256>>>(x, ew1, eb1);
    k_conv2<<<1024, 256>>>(ew2, eb2);
    k_conv3<<<1024, 256>>>(ew3, eb3);
    k_vq   <<<256, 256>>>(cb);
    k_dec1 <<<1024, 256>>>(dw1, db1);
    k_dec2 <<<2048, 256>>>(dw2, db2);
    k_dec3 <<<3907, 256>>>(dw3, db3, x, out + 3);
    k_final<<<1, 1>>>(out);
}